// round 3
// baseline (speedup 1.0000x reference)
#include <cuda_runtime.h>

#define NROWS 16384
#define DCOLS 2048
#define TPB   256
#define GRID  1184                      // 8 CTAs/SM * 148 SMs, one full wave
#define WARPS_TOTAL (GRID * 8)          // 9472 warps, warp-per-row grid-stride

// Device-global scratch (no allocations allowed).
__device__ float        g_partial[GRID];
__device__ unsigned int g_counter = 0;  // self-resetting for graph replay

__global__ void __launch_bounds__(TPB) cosine_loss_persistent(
    const float* __restrict__ cxr, const float* __restrict__ ehr,
    float* __restrict__ out)
{
    const int t    = threadIdx.x;
    const int lane = t & 31;
    const int warp = t >> 5;
    const int gw   = blockIdx.x * 8 + warp;   // global warp id

    float csum = 0.f;   // sum of cosines for this warp's rows (fixed order)

    for (int row = gw; row < NROWS; row += WARPS_TOTAL) {
        const float4* __restrict__ a = reinterpret_cast<const float4*>(ehr + (size_t)row * DCOLS);
        const float4* __restrict__ b = reinterpret_cast<const float4*>(cxr + (size_t)row * DCOLS);

        float dot = 0.f, na = 0.f, nb = 0.f;

        // 512 float4 per tensor per row; 32 lanes -> 16 float4 each.
        // Process in 8 chunks of 2 float4 per tensor; 4 loads batched (MLP=4).
        #pragma unroll
        for (int c = 0; c < 8; c++) {
            float4 a0 = a[lane + 64 * c];
            float4 b0 = b[lane + 64 * c];
            float4 a1 = a[lane + 64 * c + 32];
            float4 b1 = b[lane + 64 * c + 32];

            dot += a0.x*b0.x + a0.y*b0.y + a0.z*b0.z + a0.w*b0.w;
            na  += a0.x*a0.x + a0.y*a0.y + a0.z*a0.z + a0.w*a0.w;
            nb  += b0.x*b0.x + b0.y*b0.y + b0.z*b0.z + b0.w*b0.w;

            dot += a1.x*b1.x + a1.y*b1.y + a1.z*b1.z + a1.w*b1.w;
            na  += a1.x*a1.x + a1.y*a1.y + a1.z*a1.z + a1.w*a1.w;
            nb  += b1.x*b1.x + b1.y*b1.y + b1.z*b1.z + b1.w*b1.w;
        }

        // Warp-local reduction (no block barrier per row).
        #pragma unroll
        for (int o = 16; o > 0; o >>= 1) {
            dot += __shfl_xor_sync(0xffffffffu, dot, o);
            na  += __shfl_xor_sync(0xffffffffu, na,  o);
            nb  += __shfl_xor_sync(0xffffffffu, nb,  o);
        }

        csum += dot * rsqrtf(na * nb);
    }

    // ── Per-CTA publish: ONE smem reduce + ONE fence + ONE atomic ──
    __shared__ float swarp[8];
    __shared__ bool  s_is_last;
    if (lane == 0) swarp[warp] = csum;
    __syncthreads();

    if (t == 0) {
        float bs = 0.f;
        #pragma unroll
        for (int i = 0; i < 8; i++) bs += swarp[i];
        g_partial[blockIdx.x] = bs;
        __threadfence();                               // publish before arrive
        unsigned int old = atomicAdd(&g_counter, 1u);
        s_is_last = (old == (unsigned)(GRID - 1));
    }
    __syncthreads();

    if (!s_is_last) return;

    // ── Last CTA: deterministic reduce of 1184 partials (L2-resident) ──
    __threadfence();
    float s = 0.f;
    for (int i = t; i < GRID; i += TPB)
        s += __ldcg(&g_partial[i]);

    #pragma unroll
    for (int o = 16; o > 0; o >>= 1)
        s += __shfl_xor_sync(0xffffffffu, s, o);

    if (lane == 0) swarp[warp] = s;
    __syncthreads();

    if (t == 0) {
        float tot = 0.f;
        #pragma unroll
        for (int i = 0; i < 8; i++) tot += swarp[i];
        out[0] = 1.0f - tot / (float)NROWS;
        g_counter = 0;                                  // reset for replay
    }
}

extern "C" void kernel_launch(void* const* d_in, const int* in_sizes, int n_in,
                              void* d_out, int out_size)
{
    const float* cxr = (const float*)d_in[0];
    const float* ehr = (const float*)d_in[1];
    float* out = (float*)d_out;
    cosine_loss_persistent<<<GRID, TPB>>>(cxr, ehr, out);
}